// round 9
// baseline (speedup 1.0000x reference)
#include <cuda_runtime.h>
#include <cstdint>

typedef unsigned int u32;
typedef unsigned long long u64;

#define NT 512
#define SLEN 65544
#define NEMB 65536

// ---------------- scratch (device globals; no allocation) ----------------
__device__ __align__(16) u32 g_exp[(NEMB * 256) / 4];  // decoded exponent bytes
__device__ uint2 g_lut[4096];                          // {freq, bias = slot - cum}
__device__ u32 g_symtab[4096];

// ---------------- build fused per-slot LUT ----------------
__global__ void k_build_lut(const int* __restrict__ tables,
                            const int* __restrict__ slot_map) {
    int s = blockIdx.x * blockDim.x + threadIdx.x;
    if (s < 4096) {
        u32 sym = (u32)slot_map[s];
        u32 t = (u32)tables[sym];
        u32 freq = t >> 16;
        u32 cum = t & 0xFFFFu;
        g_lut[s] = make_uint2(freq, (u32)s - cum);
        g_symtab[s] = sym;
    }
}

// pack 4 raw int32 "bytes" big-endian-first into one u32 (first byte at MSB)
__device__ __forceinline__ u32 pack_be(int4 v) {
    u32 t1 = __byte_perm((u32)v.z, (u32)v.w, 0x0004); // b0=w0, b1=z0
    u32 t2 = __byte_perm((u32)v.x, (u32)v.y, 0x0004); // b0=y0, b1=x0
    return __byte_perm(t1, t2, 0x5410);               // [x0 y0 z0 w0]
}

// one rANS symbol step: state/window/pos/acc are per-chain registers.
// Reads happen with pos <= 5 (sh in [8,48]); refill restores pos <= 3.
#define DECODE_SYM(state, w64, pos, accw, byte_i) do {                       \
    u32 slot = (state) & 4095u;                                              \
    uint2 e = LUT[slot];                 /* on-chain LDS.64 */               \
    u32 sym = (u32)SYMT[slot];           /* off-chain */                     \
    u32 sh = 48u - 8u * (u32)(pos);                                          \
    u32 b01 = (u32)((w64) >> sh);        /* bytes[pos],[pos+1] in low 16 */  \
    u32 d = e.x * ((state) >> 12) + e.y; /* freq*(state>>12)+bias */         \
    bool p1 = d < (1u << 23);                                                \
    bool p2 = d < (1u << 15);            /* implies p1 */                    \
    u32 c1 = (d << 8) | ((b01 >> 8) & 0xFFu);                                \
    u32 c2 = (d << 16) | (b01 & 0xFFFFu);                                    \
    u32 ns = p1 ? c1 : d;                                                    \
    (state) = p2 ? c2 : ns;                                                  \
    (pos) += (int)p1 + (int)p2;                                              \
    (accw) |= sym << (8 * (byte_i));                                         \
} while (0)

// branchless refill: splice 4 bytes into the window when >=4 consumed.
// LDG is unconditional + clamped (idempotent when !need) -> no BSSY/BSYNC.
#define REFILL(w64, pos, nb, pf, idx, sp) do {                               \
    bool need = (pos) >= 4;                                                  \
    u32 w_hi = (u32)((w64) >> 32), w_lo = (u32)(w64);                        \
    w_hi = need ? w_lo : w_hi;                                               \
    w_lo = need ? (nb) : w_lo;                                               \
    (w64) = ((u64)w_hi << 32) | (u64)w_lo;                                   \
    (pos) = need ? (pos) - 4 : (pos);                                        \
    u32 nb2 = pack_be(pf);               /* off-chain PRMTs */               \
    (nb) = need ? nb2 : (nb);                                                \
    (idx) += need ? 1 : 0;                                                   \
    int ci = (idx) < 16385 ? (idx) : 16385;  /* clamp: never read OOB */     \
    (pf) = __ldg((sp) + ci);                                                 \
} while (0)

// ---------------- the serial rANS decode ----------------
// 256 one-warp CTAs (grid >= 148: no low-grid issue throttle). Lane 0 of each
// CTA runs TWO independent tile chains interleaved: while chain A waits on its
// LDS/chain latency (~85 cyc/sym), chain B's instructions issue -> ~2x tput.
__global__ void __launch_bounds__(32, 1)
k_decode(const int* __restrict__ stream,
         const int* __restrict__ tile_offsets,
         const int* __restrict__ states) {
    __shared__ uint2 LUT[4096];
    __shared__ unsigned char SYMT[4096];
    int tid = threadIdx.x;
#pragma unroll 4
    for (int i = tid; i < 4096; i += 32) {
        LUT[i] = g_lut[i];
        SYMT[i] = (unsigned char)g_symtab[i];
    }
    __syncthreads();
    if (tid != 0) return;

    int tA = blockIdx.x * 2;
    int tB = tA + 1;

    u32 stA = (u32)states[tA];
    u32 stB = (u32)states[tB];
    const int4* spA = (const int4*)(stream + tile_offsets[tA]);
    const int4* spB = (const int4*)(stream + tile_offsets[tB]);

    u64 wA = ((u64)pack_be(__ldg(spA + 0)) << 32) | (u64)pack_be(__ldg(spA + 1));
    u64 wB = ((u64)pack_be(__ldg(spB + 0)) << 32) | (u64)pack_be(__ldg(spB + 1));
    u32 nbA = pack_be(__ldg(spA + 2));
    u32 nbB = pack_be(__ldg(spB + 2));
    int4 pfA = __ldg(spA + 3);
    int4 pfB = __ldg(spB + 3);
    int idxA = 3, idxB = 3;   // int4 index pf currently holds
    int posA = 0, posB = 0;   // bytes consumed from window

    uint4* outp = (uint4*)g_exp;
    u32 obA = (u32)(tA >> 3) * 16384u + (u32)(tA & 7) * 2u;
    u32 obB = (u32)(tB >> 3) * 16384u + (u32)(tB & 7) * 2u;

    for (int i = 0; i < 2048; ++i) {           // 16 symbols per chain per iter
        u32 waccA[4], waccB[4];
#pragma unroll
        for (int j = 0; j < 4; ++j) {
            u32 accA = 0, accB = 0;
#pragma unroll
            for (int g = 0; g < 2; ++g) {
                DECODE_SYM(stA, wA, posA, accA, 2 * g + 0);
                DECODE_SYM(stB, wB, posB, accB, 2 * g + 0);
                DECODE_SYM(stA, wA, posA, accA, 2 * g + 1);
                DECODE_SYM(stB, wB, posB, accB, 2 * g + 1);
                REFILL(wA, posA, nbA, pfA, idxA, spA);
                REFILL(wB, posB, nbB, pfB, idxB, spB);
            }
            waccA[j] = accA;
            waccB[j] = accB;
        }
        outp[obA] = make_uint4(waccA[0], waccA[1], waccA[2], waccA[3]);
        outp[obB] = make_uint4(waccB[0], waccB[1], waccB[2], waccB[3]);
        u32 step = (i & 1) ? 15u : 1u;         // half0->half1: +1; next k: +15
        obA += step;
        obB += step;
    }
}

// ---------------- gather: out[l, :] = f32(bf16(exp<<8 | man)) of row x[l] ----------------
__global__ void __launch_bounds__(256)
k_gather(const int* __restrict__ x, const int4* __restrict__ man,
         float4* __restrict__ out) {
    int l = blockIdx.x * 4 + (threadIdx.x >> 6);
    int c = threadIdx.x & 63;
    int row = x[l];
    u32 e = g_exp[row * 64 + c];
    int4 m = __ldg(man + row * 64 + c);  // raw int32 mantissa bytes
    float4 o;
    o.x = __uint_as_float(((e & 0xFFu) << 24) | (((u32)m.x & 0xFFu) << 16));
    o.y = __uint_as_float((((e >> 8) & 0xFFu) << 24) | (((u32)m.y & 0xFFu) << 16));
    o.z = __uint_as_float((((e >> 16) & 0xFFu) << 24) | (((u32)m.z & 0xFFu) << 16));
    o.w = __uint_as_float((e & 0xFF000000u) | (((u32)m.w & 0xFFu) << 16));
    out[(size_t)l * 64 + (size_t)c] = o;
}

// ---------------- launch ----------------
extern "C" void kernel_launch(void* const* d_in, const int* in_sizes, int n_in,
                              void* d_out, int out_size) {
    const int* x       = (const int*)d_in[0];
    const int* stream  = (const int*)d_in[1];
    const int* states  = (const int*)d_in[2];
    const int* tables  = (const int*)d_in[3];
    const int* slotmap = (const int*)d_in[4];
    const int* toffs   = (const int*)d_in[5];
    // d_in[6] = tile_max_lens (uniform; unused)
    const int* manraw  = (const int*)d_in[7];
    float* out = (float*)d_out;

    k_build_lut<<<16, 256>>>(tables, slotmap);
    k_decode<<<256, 32>>>(stream, toffs, states);
    k_gather<<<65536, 256>>>(x, (const int4*)manraw, (float4*)out);
}

// round 10
// speedup vs baseline: 1.1693x; 1.1693x over previous
#include <cuda_runtime.h>
#include <cstdint>

typedef unsigned int u32;
typedef unsigned long long u64;

#define NT 512
#define SLEN 65544
#define NEMB 65536

// ---------------- scratch (device globals; no allocation) ----------------
__device__ __align__(16) u32 g_exp[(NEMB * 256) / 4];  // decoded exponent bytes
__device__ u32 g_man[(NEMB * 256) / 4];                // packed mantissa bytes
__device__ uint2 g_lut[4096];                          // {freq, bias = slot - cum}
__device__ u32 g_symtab[4096];

// ---------------- build fused per-slot LUT ----------------
__global__ void k_build_lut(const int* __restrict__ tables,
                            const int* __restrict__ slot_map) {
    int s = blockIdx.x * blockDim.x + threadIdx.x;
    if (s < 4096) {
        u32 sym = (u32)slot_map[s];
        u32 t = (u32)tables[sym];
        u32 freq = t >> 16;
        u32 cum = t & 0xFFFFu;
        g_lut[s] = make_uint2(freq, (u32)s - cum);
        g_symtab[s] = sym;
    }
}

// ---------------- pack mantissa int32 bytes for the gather ----------------
__global__ void k_pack_man(const int4* __restrict__ in, int n4) {
    int i = blockIdx.x * blockDim.x + threadIdx.x;
    if (i < n4) {
        int4 v = in[i];
        g_man[i] = (u32)(v.x & 0xFF) | ((u32)(v.y & 0xFF) << 8) |
                   ((u32)(v.z & 0xFF) << 16) | ((u32)(v.w & 0xFF) << 24);
    }
}

// pack 4 raw int32 "bytes" big-endian-first into one u32 (first byte at MSB)
__device__ __forceinline__ u32 pack_be(int4 v) {
    u32 t1 = __byte_perm((u32)v.z, (u32)v.w, 0x0004); // b0=w0, b1=z0
    u32 t2 = __byte_perm((u32)v.x, (u32)v.y, 0x0004); // b0=y0, b1=x0
    return __byte_perm(t1, t2, 0x5410);               // [x0 y0 z0 w0]
}

// one rANS symbol step: state/window/pos/acc are per-chain registers.
#define DECODE_SYM(state, w64, pos, accw, byte_i) do {                       \
    u32 slot = (state) & 4095u;                                              \
    uint2 e = LUT[slot];                 /* on-chain LDS.64 */               \
    u32 sym = (u32)SYMT[slot];           /* off-chain */                     \
    u32 sh = 48u - 8u * (u32)(pos);                                          \
    u32 b01 = (u32)((w64) >> sh);        /* bytes[pos],[pos+1] in low 16 */  \
    u32 d = e.x * ((state) >> 12) + e.y; /* freq*(state>>12)+bias */         \
    bool p1 = d < (1u << 23);                                                \
    bool p2 = d < (1u << 15);            /* implies p1 */                    \
    u32 c1 = (d << 8) | ((b01 >> 8) & 0xFFu);                                \
    u32 c2 = (d << 16) | (b01 & 0xFFFFu);                                    \
    u32 ns = p1 ? c1 : d;                                                    \
    (state) = p2 ? c2 : ns;                                                  \
    (pos) += (int)p1 + (int)p2;                                              \
    (accw) |= sym << (8 * (byte_i));                                         \
} while (0)

// branchless refill: splice 4 bytes into the window when >=4 consumed.
// LDG is unconditional + clamped (idempotent when !need) -> no BSSY/BSYNC.
#define REFILL(w64, pos, nb, pf, idx, sp) do {                               \
    bool need = (pos) >= 4;                                                  \
    u32 w_hi = (u32)((w64) >> 32), w_lo = (u32)(w64);                        \
    w_hi = need ? w_lo : w_hi;                                               \
    w_lo = need ? (nb) : w_lo;                                               \
    (w64) = ((u64)w_hi << 32) | (u64)w_lo;                                   \
    (pos) = need ? (pos) - 4 : (pos);                                        \
    u32 nb2 = pack_be(pf);               /* off-chain PRMTs */               \
    (nb) = need ? nb2 : (nb);                                                \
    (idx) += need ? 1 : 0;                                                   \
    int ci = (idx) < 16385 ? (idx) : 16385;  /* clamp: never read OOB */     \
    (pf) = __ldg((sp) + ci);                                                 \
} while (0)

// ---------------- the serial rANS decode ----------------
// 256 one-warp CTAs (grid >= 148). Lanes 0 and 1 of each warp decode one tile
// each: the ~30-instruction symbol body is issued ONCE for both chains (SIMT),
// halving the per-warp ALU issue-rate pressure (rt_SMSP=2/op) while keeping
// all 512 chains live. Body is branchless -> the two lanes never diverge.
__global__ void __launch_bounds__(32, 1)
k_decode(const int* __restrict__ stream,
         const int* __restrict__ tile_offsets,
         const int* __restrict__ states) {
    __shared__ uint2 LUT[4096];
    __shared__ unsigned char SYMT[4096];
    int tid = threadIdx.x;
#pragma unroll 4
    for (int i = tid; i < 4096; i += 32) {
        LUT[i] = g_lut[i];
        SYMT[i] = (unsigned char)g_symtab[i];
    }
    __syncthreads();
    if (tid >= 2) return;

    int tile = blockIdx.x * 2 + tid;
    u32 state = (u32)states[tile];
    const int4* sp = (const int4*)(stream + tile_offsets[tile]);

    // 8-byte static window (MSB = next stream byte) + pos = bytes consumed.
    u64 w64 = ((u64)pack_be(__ldg(sp + 0)) << 32) | (u64)pack_be(__ldg(sp + 1));
    u32 nb = pack_be(__ldg(sp + 2));
    int4 pf = __ldg(sp + 3);
    int idx = 3;      // int4 index pf currently holds
    int pos = 0;      // bytes consumed from w64 (invariant: <=3 at group start)

    int rt = tile >> 3, ct = tile & 7;
    uint4* outp = (uint4*)g_exp;
    u32 ob = (u32)rt * 16384u + (u32)ct * 2u;  // uint4 index for (k=0, half=0)

    for (int i = 0; i < 2048; ++i) {           // 16 symbols per iteration
        u32 wacc[4];
#pragma unroll
        for (int j = 0; j < 4; ++j) {          // one output u32 word = 4 symbols
            u32 accw = 0;
#pragma unroll
            for (int g = 0; g < 2; ++g) {      // 2 symbols + refill
                DECODE_SYM(state, w64, pos, accw, 2 * g + 0);
                DECODE_SYM(state, w64, pos, accw, 2 * g + 1);
                REFILL(w64, pos, nb, pf, idx, sp);
            }
            wacc[j] = accw;
        }
        outp[ob] = make_uint4(wacc[0], wacc[1], wacc[2], wacc[3]);
        ob += (i & 1) ? 15u : 1u;              // half0->half1: +1; then next k: +15
    }
}

// ---------------- gather: out[l, :] = f32(bf16(exp<<8 | man)) of row x[l] ----------------
__global__ void __launch_bounds__(256)
k_gather(const int* __restrict__ x, float4* __restrict__ out) {
    int l = blockIdx.x * 4 + (threadIdx.x >> 6);
    int c = threadIdx.x & 63;
    int row = x[l];
    u32 e = g_exp[row * 64 + c];
    u32 m = g_man[row * 64 + c];
    float4 o;
    o.x = __uint_as_float(((e & 0xFFu) << 24) | ((m & 0xFFu) << 16));
    o.y = __uint_as_float((((e >> 8) & 0xFFu) << 24) | (((m >> 8) & 0xFFu) << 16));
    o.z = __uint_as_float((((e >> 16) & 0xFFu) << 24) | (((m >> 16) & 0xFFu) << 16));
    o.w = __uint_as_float((e & 0xFF000000u) | ((m >> 24) << 16));
    out[(size_t)l * 64 + (size_t)c] = o;
}

// ---------------- launch ----------------
extern "C" void kernel_launch(void* const* d_in, const int* in_sizes, int n_in,
                              void* d_out, int out_size) {
    const int* x       = (const int*)d_in[0];
    const int* stream  = (const int*)d_in[1];
    const int* states  = (const int*)d_in[2];
    const int* tables  = (const int*)d_in[3];
    const int* slotmap = (const int*)d_in[4];
    const int* toffs   = (const int*)d_in[5];
    // d_in[6] = tile_max_lens (uniform; unused)
    const int* manraw  = (const int*)d_in[7];
    float* out = (float*)d_out;

    k_build_lut<<<16, 256>>>(tables, slotmap);

    int n4m = (NEMB * 256) / 4;         // 4,194,304
    k_pack_man<<<(n4m + 255) / 256, 256>>>((const int4*)manraw, n4m);

    k_decode<<<256, 32>>>(stream, toffs, states);

    k_gather<<<65536, 256>>>(x, (float4*)out);
}

// round 13
// speedup vs baseline: 1.2982x; 1.1102x over previous
#include <cuda_runtime.h>
#include <cstdint>

typedef unsigned int u32;
typedef unsigned long long u64;

#define NT 512
#define SLEN 65544
#define NEMB 65536

// ---------------- scratch (device globals; no allocation) ----------------
__device__ __align__(16) u32 g_exp[(NEMB * 256) / 4];  // decoded exponent bytes
__device__ u32 g_man[(NEMB * 256) / 4];                // packed mantissa bytes
__device__ uint2 g_lut[4096];                          // {freq, bias = slot - cum}
__device__ u32 g_symtab[4096];

// ---------------- build fused per-slot LUT ----------------
__global__ void k_build_lut(const int* __restrict__ tables,
                            const int* __restrict__ slot_map) {
    int s = blockIdx.x * blockDim.x + threadIdx.x;
    if (s < 4096) {
        u32 sym = (u32)slot_map[s];
        u32 t = (u32)tables[sym];
        u32 freq = t >> 16;
        u32 cum = t & 0xFFFFu;
        g_lut[s] = make_uint2(freq, (u32)s - cum);
        g_symtab[s] = sym;
    }
}

// ---------------- pack mantissa int32 bytes for the gather ----------------
__global__ void k_pack_man(const int4* __restrict__ in, int n4) {
    int i = blockIdx.x * blockDim.x + threadIdx.x;
    if (i < n4) {
        int4 v = in[i];
        g_man[i] = (u32)(v.x & 0xFF) | ((u32)(v.y & 0xFF) << 8) |
                   ((u32)(v.z & 0xFF) << 16) | ((u32)(v.w & 0xFF) << 24);
    }
}

// pack 4 raw int32 "bytes" big-endian-first into one u32 (first byte at MSB)
__device__ __forceinline__ u32 pack_be(int4 v) {
    u32 t1 = __byte_perm((u32)v.z, (u32)v.w, 0x0004); // b0=w0, b1=z0
    u32 t2 = __byte_perm((u32)v.x, (u32)v.y, 0x0004); // b0=y0, b1=x0
    return __byte_perm(t1, t2, 0x5410);               // [x0 y0 z0 w0]
}

// one rANS symbol. Shifting-window design: w64 keeps the unconsumed stream
// left-aligned (MSB = next byte), so T = w64>>32 is ready AT SYMBOL START and
// the renorm candidates are single PRMTs issuing in parallel with the ISETPs.
// Critical cycle: LOP3 -> IMAD(addr) -> LDS.64 -> IMAD -> ISETP -> SEL -> SEL.
#define DECODE_SYM(state, w64, fill, accw, byte_i) do {                      \
    u32 slot = (state) & 4095u;                                              \
    uint2 e = LUT[slot];                  /* on-chain LDS.64 */              \
    u32 sym = (u32)SYMT[slot];            /* off-chain */                    \
    u32 T = (u32)((w64) >> 32);           /* next bytes: T.b3=b0, T.b2=b1 */ \
    u32 d = e.x * ((state) >> 12) + e.y;  /* freq*(state>>12)+bias */        \
    u32 c1 = __byte_perm(d, T, 0x2107);   /* (d<<8)|b0        : 1 PRMT */   \
    u32 c2 = __byte_perm(d, T, 0x1076);   /* (d<<16)|b0b1     : 1 PRMT */   \
    bool p1 = d < (1u << 23);                                                \
    bool p2 = d < (1u << 15);             /* implies p1 */                   \
    u32 t = p2 ? c2 : c1;                                                    \
    (state) = p1 ? t : d;                                                    \
    u32 sh = p1 ? (p2 ? 16u : 8u) : 0u;   /* parallel short cycle */         \
    (w64) <<= sh;                                                            \
    (fill) -= (int)p1 + (int)p2;                                             \
    (accw) |= sym << (8 * (byte_i));                                         \
} while (0)

// branchless refill every 2 symbols: splice 4 bytes right below the `fill`
// valid top bytes whenever fill <= 4 (restores fill in [4,8]; per-pair
// consumption <= 4 keeps it balanced). LDG unconditional + clamped.
#define REFILL(w64, fill, nb, pf, idx, sp) do {                              \
    bool need = (fill) <= 4;                                                 \
    u32 f4 = need ? (u32)(fill) : 4u;                                        \
    u64 spl = ((u64)(nb)) << (32u - 8u * f4);                                \
    (w64) = need ? ((w64) | spl) : (w64);                                    \
    (fill) = need ? (fill) + 4 : (fill);                                     \
    u32 nb2 = pack_be(pf);                /* off-chain PRMTs */              \
    (nb) = need ? nb2 : (nb);                                                \
    (idx) += need ? 1 : 0;                                                   \
    int ci = (idx) < 16385 ? (idx) : 16385;  /* clamp: never read OOB */     \
    (pf) = __ldg((sp) + ci);                                                 \
} while (0)

// ---------------- the serial rANS decode ----------------
// 512 one-warp CTAs (best-measured geometry). Lane 0 runs the chain alone.
__global__ void __launch_bounds__(32, 1)
k_decode(const int* __restrict__ stream,
         const int* __restrict__ tile_offsets,
         const int* __restrict__ states) {
    __shared__ uint2 LUT[4096];
    __shared__ unsigned char SYMT[4096];
    int tid = threadIdx.x;
#pragma unroll 4
    for (int i = tid; i < 4096; i += 32) {
        LUT[i] = g_lut[i];
        SYMT[i] = (unsigned char)g_symtab[i];
    }
    __syncthreads();
    if (tid != 0) return;

    int tile = blockIdx.x;
    u32 state = (u32)states[tile];
    const int4* sp = (const int4*)(stream + tile_offsets[tile]);

    // left-aligned shifting window + 2-deep refill pipeline
    u64 w64 = ((u64)pack_be(__ldg(sp + 0)) << 32) | (u64)pack_be(__ldg(sp + 1));
    u32 nb = pack_be(__ldg(sp + 2));
    int4 pf = __ldg(sp + 3);
    int idx = 3;      // int4 index pf currently holds
    int fill = 8;     // valid bytes in w64 (>=4 at every pair start)

    int rt = tile >> 3, ct = tile & 7;
    uint4* outp = (uint4*)g_exp;
    u32 ob = (u32)rt * 16384u + (u32)ct * 2u;  // uint4 index for (k=0, half=0)

    for (int i = 0; i < 2048; ++i) {           // 16 symbols per iteration
        u32 wacc[4];
#pragma unroll
        for (int j = 0; j < 4; ++j) {          // one output u32 word = 4 symbols
            u32 accw = 0;
#pragma unroll
            for (int g = 0; g < 2; ++g) {      // 2 symbols + refill
                DECODE_SYM(state, w64, fill, accw, 2 * g + 0);
                DECODE_SYM(state, w64, fill, accw, 2 * g + 1);
                REFILL(w64, fill, nb, pf, idx, sp);
            }
            wacc[j] = accw;
        }
        outp[ob] = make_uint4(wacc[0], wacc[1], wacc[2], wacc[3]);
        ob += (i & 1) ? 15u : 1u;              // half0->half1: +1; then next k: +15
    }
}

// ---------------- gather: out[l, :] = f32(bf16(exp<<8 | man)) of row x[l] ----------------
__global__ void __launch_bounds__(256)
k_gather(const int* __restrict__ x, float4* __restrict__ out) {
    int l = blockIdx.x * 4 + (threadIdx.x >> 6);
    int c = threadIdx.x & 63;
    int row = x[l];
    u32 e = g_exp[row * 64 + c];
    u32 m = g_man[row * 64 + c];
    float4 o;
    o.x = __uint_as_float(((e & 0xFFu) << 24) | ((m & 0xFFu) << 16));
    o.y = __uint_as_float((((e >> 8) & 0xFFu) << 24) | (((m >> 8) & 0xFFu) << 16));
    o.z = __uint_as_float((((e >> 16) & 0xFFu) << 24) | (((m >> 16) & 0xFFu) << 16));
    o.w = __uint_as_float((e & 0xFF000000u) | ((m >> 24) << 16));
    out[(size_t)l * 64 + (size_t)c] = o;
}

// ---------------- launch ----------------
extern "C" void kernel_launch(void* const* d_in, const int* in_sizes, int n_in,
                              void* d_out, int out_size) {
    const int* x       = (const int*)d_in[0];
    const int* stream  = (const int*)d_in[1];
    const int* states  = (const int*)d_in[2];
    const int* tables  = (const int*)d_in[3];
    const int* slotmap = (const int*)d_in[4];
    const int* toffs   = (const int*)d_in[5];
    // d_in[6] = tile_max_lens (uniform; unused)
    const int* manraw  = (const int*)d_in[7];
    float* out = (float*)d_out;

    k_build_lut<<<16, 256>>>(tables, slotmap);

    int n4m = (NEMB * 256) / 4;         // 4,194,304
    k_pack_man<<<(n4m + 255) / 256, 256>>>((const int4*)manraw, n4m);

    k_decode<<<512, 32>>>(stream, toffs, states);

    k_gather<<<65536, 256>>>(x, (float4*)out);
}